// round 1
// baseline (speedup 1.0000x reference)
#include <cuda_runtime.h>
#include <math.h>

// Problem constants
#define Lc 2
#define Bc 4
#define Tc 1024
#define Dc 256
#define Hc 4
#define Mc 1024
#define NROWS (Bc*Tc)      // 4096
#define HD (Hc*Dc)         // 1024
#define LN_EPS 1e-5f

// Scratch (device globals; allocation-free contract)
__device__ float g_x[NROWS*Dc];          // 4 MB   residual stream
__device__ float g_q[NROWS*HD];          // 16 MB
__device__ float g_k[NROWS*HD];          // 16 MB
__device__ float g_v[NROWS*HD];          // 16 MB
__device__ float g_ao[NROWS*HD];         // 16 MB  attn output (pre-Wo)
__device__ float g_h[NROWS*Mc];          // 16 MB  MLP hidden
__device__ float g_proj[NROWS*Dc];       // 4 MB
__device__ float g_s[(long)Bc*Hc*Tc*Tc]; // 64 MB  attention scores

// ---------------------------------------------------------------------------
// Generic tiled GEMM: C = op( alpha * (A @ B(^T) + bias) )
// 64x64 tile, BK=16, 256 threads, 4x4 per thread.
// Batch via blockIdx.z: offset = (z/zdiv)*s1 + (z%zdiv)*s2 per operand.
// flags: bit0 = transB (C[m,n] = sum_k A[m,k]*B[n,k]), bit1 = ReLU
// ---------------------------------------------------------------------------
#define BM 64
#define BN 64
#define BK 16

__global__ void __launch_bounds__(256) gemm_k(
    const float* __restrict__ A, const float* __restrict__ Bm,
    float* __restrict__ C, const float* __restrict__ bias,
    int K, int lda, int ldb, int ldc,
    long sA1, long sA2, long sB1, long sB2, long sC1, long sC2,
    int zdiv, float alpha, int flags)
{
    int z  = blockIdx.z;
    int zq = z / zdiv, zr = z % zdiv;
    A  += (long)zq * sA1 + (long)zr * sA2;
    Bm += (long)zq * sB1 + (long)zr * sB2;
    C  += (long)zq * sC1 + (long)zr * sC2;

    __shared__ float As[BK][BM];
    __shared__ float Bs[BK][BN];

    int t  = threadIdx.x;
    int tx = t & 15, ty = t >> 4;
    int rowBase = blockIdx.y * BM;
    int colBase = blockIdx.x * BN;

    float acc[4][4] = {};
    const bool transB = (flags & 1);

    for (int k0 = 0; k0 < K; k0 += BK) {
        {   // A tile: 64 rows x 16 k, transposed into As[k][m]
            int m = t >> 2;
            int k = (t & 3) * 4;
            float4 av = *(const float4*)&A[(long)(rowBase + m) * lda + k0 + k];
            As[k+0][m] = av.x; As[k+1][m] = av.y; As[k+2][m] = av.z; As[k+3][m] = av.w;
        }
        if (!transB) {
            int k = t >> 4;
            int n = (t & 15) * 4;
            float4 bv = *(const float4*)&Bm[(long)(k0 + k) * ldb + colBase + n];
            *(float4*)&Bs[k][n] = bv;
        } else {
            int n = t >> 2;
            int k = (t & 3) * 4;
            float4 bv = *(const float4*)&Bm[(long)(colBase + n) * ldb + k0 + k];
            Bs[k+0][n] = bv.x; Bs[k+1][n] = bv.y; Bs[k+2][n] = bv.z; Bs[k+3][n] = bv.w;
        }
        __syncthreads();

        #pragma unroll
        for (int k = 0; k < BK; k++) {
            float4 a = *(float4*)&As[k][ty * 4];
            float4 b = *(float4*)&Bs[k][tx * 4];
            float ar[4] = {a.x, a.y, a.z, a.w};
            float br[4] = {b.x, b.y, b.z, b.w};
            #pragma unroll
            for (int i = 0; i < 4; i++)
                #pragma unroll
                for (int j = 0; j < 4; j++)
                    acc[i][j] = fmaf(ar[i], br[j], acc[i][j]);
        }
        __syncthreads();
    }

    #pragma unroll
    for (int i = 0; i < 4; i++) {
        int r = rowBase + ty * 4 + i;
        #pragma unroll
        for (int j = 0; j < 4; j++) {
            int c = colBase + tx * 4 + j;
            float v = acc[i][j];
            if (bias) v += bias[c];
            v *= alpha;
            if (flags & 2) v = fmaxf(v, 0.0f);
            C[(long)r * ldc + c] = v;
        }
    }
}

// ---------------------------------------------------------------------------
// Row softmax over rows of length Tc=1024. One block (256 thr) per row.
// ---------------------------------------------------------------------------
__global__ void __launch_bounds__(256) softmax_k(float* __restrict__ S)
{
    float* row = S + (long)blockIdx.x * Tc;
    int t = threadIdx.x;
    float4 v = *(float4*)&row[t * 4];

    __shared__ float red[8];

    float m = fmaxf(fmaxf(v.x, v.y), fmaxf(v.z, v.w));
    #pragma unroll
    for (int o = 16; o > 0; o >>= 1) m = fmaxf(m, __shfl_xor_sync(0xffffffffu, m, o));
    if ((t & 31) == 0) red[t >> 5] = m;
    __syncthreads();
    m = red[0];
    #pragma unroll
    for (int w = 1; w < 8; w++) m = fmaxf(m, red[w]);

    v.x = __expf(v.x - m); v.y = __expf(v.y - m);
    v.z = __expf(v.z - m); v.w = __expf(v.w - m);
    float s = v.x + v.y + v.z + v.w;
    #pragma unroll
    for (int o = 16; o > 0; o >>= 1) s += __shfl_xor_sync(0xffffffffu, s, o);
    __syncthreads();
    if ((t & 31) == 0) red[t >> 5] = s;
    __syncthreads();
    s = 0.0f;
    #pragma unroll
    for (int w = 0; w < 8; w++) s += red[w];

    float inv = 1.0f / s;
    v.x *= inv; v.y *= inv; v.z *= inv; v.w *= inv;
    *(float4*)&row[t * 4] = v;
}

// ---------------------------------------------------------------------------
// Fused residual + LayerNorm: out = LN(a + res) * sg + bg.  One block per row
// (Dc = 256 threads). out may alias res (block-local read-before-write).
// ---------------------------------------------------------------------------
__global__ void __launch_bounds__(256) ln_k(
    const float* __restrict__ a, const float* __restrict__ res,
    const float* __restrict__ sg, const float* __restrict__ bg,
    float* __restrict__ out)
{
    long r = blockIdx.x;
    int  t = threadIdx.x;
    float v = a[r * Dc + t] + res[r * Dc + t];

    __shared__ float red[8];

    float s = v;
    #pragma unroll
    for (int o = 16; o > 0; o >>= 1) s += __shfl_xor_sync(0xffffffffu, s, o);
    if ((t & 31) == 0) red[t >> 5] = s;
    __syncthreads();
    s = 0.0f;
    #pragma unroll
    for (int w = 0; w < 8; w++) s += red[w];
    float mean = s * (1.0f / Dc);

    float d = v - mean;
    float q = d * d;
    #pragma unroll
    for (int o = 16; o > 0; o >>= 1) q += __shfl_xor_sync(0xffffffffu, q, o);
    __syncthreads();
    if ((t & 31) == 0) red[t >> 5] = q;
    __syncthreads();
    q = 0.0f;
    #pragma unroll
    for (int w = 0; w < 8; w++) q += red[w];
    float var = q * (1.0f / Dc);

    out[r * Dc + t] = d * rsqrtf(var + LN_EPS) * sg[t] + bg[t];
}

// ---------------------------------------------------------------------------
// Launch
// ---------------------------------------------------------------------------
extern "C" void kernel_launch(void* const* d_in, const int* in_sizes, int n_in,
                              void* d_out, int out_size)
{
    const float* queries = (const float*)d_in[0];
    const float* Wq   = (const float*)d_in[1];
    const float* bq   = (const float*)d_in[2];
    const float* Wk   = (const float*)d_in[3];
    const float* bk   = (const float*)d_in[4];
    const float* Wv   = (const float*)d_in[5];
    const float* bv   = (const float*)d_in[6];
    const float* Wo   = (const float*)d_in[7];
    const float* bo   = (const float*)d_in[8];
    const float* ln1s = (const float*)d_in[9];
    const float* ln1b = (const float*)d_in[10];
    const float* W1   = (const float*)d_in[11];
    const float* b1   = (const float*)d_in[12];
    const float* W2   = (const float*)d_in[13];
    const float* b2   = (const float*)d_in[14];
    const float* ln2s = (const float*)d_in[15];
    const float* ln2b = (const float*)d_in[16];

    float *x, *q, *k, *v, *ao, *h, *proj, *sc;
    cudaGetSymbolAddress((void**)&x,    g_x);
    cudaGetSymbolAddress((void**)&q,    g_q);
    cudaGetSymbolAddress((void**)&k,    g_k);
    cudaGetSymbolAddress((void**)&v,    g_v);
    cudaGetSymbolAddress((void**)&ao,   g_ao);
    cudaGetSymbolAddress((void**)&h,    g_h);
    cudaGetSymbolAddress((void**)&proj, g_proj);
    cudaGetSymbolAddress((void**)&sc,   g_s);

    const float* xin = queries;  // residual stream input for the layer
    const float qscale = 1.0f / 16.0f;  // 1/sqrt(D), D=256

    for (int l = 0; l < Lc; l++) {
        const float* wq  = Wq + (long)l * Dc * HD;
        const float* wk  = Wk + (long)l * Dc * HD;
        const float* wv  = Wv + (long)l * Dc * HD;
        const float* wo  = Wo + (long)l * HD * Dc;
        const float* w1  = W1 + (long)l * Dc * Mc;
        const float* w2  = W2 + (long)l * Mc * Dc;
        const float* bql = bq + (long)l * HD;
        const float* bkl = bk + (long)l * HD;
        const float* bvl = bv + (long)l * HD;
        const float* bol = bo + (long)l * Dc;
        const float* b1l = b1 + (long)l * Mc;
        const float* b2l = b2 + (long)l * Dc;
        const float* s1l = ln1s + (long)l * Dc;
        const float* o1l = ln1b + (long)l * Dc;
        const float* s2l = ln2s + (long)l * Dc;
        const float* o2l = ln2b + (long)l * Dc;

        // QKV projections: [4096,256]x[256,1024]
        gemm_k<<<dim3(HD/BN, NROWS/BM, 1), 256>>>(xin, wq, q, bql,
            Dc, Dc, HD, HD, 0,0,0,0,0,0, 1, qscale, 0);
        gemm_k<<<dim3(HD/BN, NROWS/BM, 1), 256>>>(xin, wk, k, bkl,
            Dc, Dc, HD, HD, 0,0,0,0,0,0, 1, 1.0f, 0);
        gemm_k<<<dim3(HD/BN, NROWS/BM, 1), 256>>>(xin, wv, v, bvl,
            Dc, Dc, HD, HD, 0,0,0,0,0,0, 1, 1.0f, 0);

        // scores[b,h] = q[b,:,h,:] @ k[b,:,h,:]^T   (16 batches, 1024x1024x256)
        gemm_k<<<dim3(Tc/BN, Tc/BM, Bc*Hc), 256>>>(q, k, sc, nullptr,
            Dc, HD, HD, Tc,
            (long)Tc*HD, (long)Dc,          // A: b-stride, h-stride
            (long)Tc*HD, (long)Dc,          // B
            (long)Hc*Tc*Tc, (long)Tc*Tc,    // C
            Hc, 1.0f, 1 /*transB*/);

        softmax_k<<<Bc*Hc*Tc, 256>>>(sc);

        // out[b,:,h,:] = scores[b,h] @ v[b,:,h,:]   (16 batches, 1024x256x1024)
        gemm_k<<<dim3(Dc/BN, Tc/BM, Bc*Hc), 256>>>(sc, v, ao, nullptr,
            Tc, Tc, HD, HD,
            (long)Hc*Tc*Tc, (long)Tc*Tc,
            (long)Tc*HD, (long)Dc,
            (long)Tc*HD, (long)Dc,
            Hc, 1.0f, 0);

        // output projection: [4096,1024]x[1024,256]
        gemm_k<<<dim3(Dc/BN, NROWS/BM, 1), 256>>>(ao, wo, proj, bol,
            HD, HD, Dc, Dc, 0,0,0,0,0,0, 1, 1.0f, 0);

        // x = LN(proj + xin)
        ln_k<<<NROWS, 256>>>(proj, xin, s1l, o1l, x);

        // MLP
        gemm_k<<<dim3(Mc/BN, NROWS/BM, 1), 256>>>(x, w1, h, b1l,
            Dc, Dc, Mc, Mc, 0,0,0,0,0,0, 1, 1.0f, 2 /*ReLU*/);
        gemm_k<<<dim3(Dc/BN, NROWS/BM, 1), 256>>>(h, w2, proj, b2l,
            Mc, Mc, Dc, Dc, 0,0,0,0,0,0, 1, 1.0f, 0);

        float* lnout = (l == Lc - 1) ? (float*)d_out : x;
        ln_k<<<NROWS, 256>>>(proj, x, s2l, o2l, lnout);

        xin = x;
    }
}

// round 3
// speedup vs baseline: 2.2213x; 2.2213x over previous
#include <cuda_runtime.h>
#include <cstdint>
#include <math.h>

// Problem constants
#define Lc 2
#define Bc 4
#define Tc 1024
#define Dc 256
#define Hc 4
#define Mc 1024
#define NROWS (Bc*Tc)      // 4096
#define HD (Hc*Dc)         // 1024
#define LN_EPS 1e-5f

// ---------------------------------------------------------------------------
// Scratch (device globals; allocation-free contract)
// ---------------------------------------------------------------------------
__device__ float g_x[NROWS*Dc];
__device__ float g_q[NROWS*HD];
__device__ float g_k[NROWS*HD];
__device__ float g_v[NROWS*HD];
__device__ float g_vt[Bc*Hc*Dc*Tc];        // V^T per (b,h): [256,1024]
__device__ float g_ao[NROWS*HD];
__device__ float g_h[NROWS*Mc];
__device__ float g_proj[NROWS*Dc];
__device__ float g_s[(long)Bc*Hc*Tc*Tc];   // attention scores
__device__ float g_wqT[HD*Dc];
__device__ float g_wkT[HD*Dc];
__device__ float g_wvT[HD*Dc];
__device__ float g_woT[Dc*HD];
__device__ float g_w1T[Mc*Dc];
__device__ float g_w2T[Dc*Mc];

// ---------------------------------------------------------------------------
// Helpers
// ---------------------------------------------------------------------------
__device__ __forceinline__ uint32_t smem_u32(const void* p) {
    uint32_t a;
    asm("{ .reg .u64 t; cvta.to.shared.u64 t, %1; cvt.u32.u64 %0, t; }"
        : "=r"(a) : "l"(p));
    return a;
}
__device__ __forceinline__ uint32_t f2tf(float f) {
    uint32_t u;
    asm("cvt.rna.tf32.f32 %0, %1;" : "=r"(u) : "f"(f));
    return u;
}
__device__ __forceinline__ void cp16(uint32_t dst, const void* src) {
    asm volatile("cp.async.cg.shared.global [%0], [%1], 16;"
                 :: "r"(dst), "l"(src) : "memory");
}
#define CP_COMMIT() asm volatile("cp.async.commit_group;" ::: "memory")
#define CP_WAIT(n)  asm volatile("cp.async.wait_group %0;" :: "n"(n) : "memory")

__device__ __forceinline__ void mma_tf32(float* c, const uint32_t* a, const uint32_t* b) {
    asm volatile(
        "mma.sync.aligned.m16n8k8.row.col.f32.tf32.tf32.f32 "
        "{%0,%1,%2,%3}, {%4,%5,%6,%7}, {%8,%9}, {%0,%1,%2,%3};"
        : "+f"(c[0]), "+f"(c[1]), "+f"(c[2]), "+f"(c[3])
        : "r"(a[0]), "r"(a[1]), "r"(a[2]), "r"(a[3]), "r"(b[0]), "r"(b[1]));
}

// ---------------------------------------------------------------------------
// tf32 mma.sync GEMM: C[m,n] = op(alpha*(sum_k A[m,k]*B[n,k] + bias[n]))
// CTA tile 128x128, BK=32, 8 warps x (32x64). flags bit1 = ReLU.
// Batch via blockIdx.z with split strides (z = zq*zdiv + zr).
// SMEM: 2 stages x (A 128x36f + B 128x36f) = 73728 B, padded stride 36.
// ---------------------------------------------------------------------------
#define SROW 36
#define SZ   (128*SROW)            // floats per operand per stage
#define GT_SMEM (4*SZ*4)           // bytes

__global__ void __launch_bounds__(256, 2) gemm_mma(
    const float* __restrict__ A, const float* __restrict__ Bm,
    float* __restrict__ C, const float* __restrict__ bias,
    int K, int lda, int ldb, int ldc,
    long sA1, long sA2, long sB1, long sB2, long sC1, long sC2,
    int zdiv, float alpha, int flags)
{
    extern __shared__ float smem[];
    uint32_t sbase = smem_u32(smem);

    int z  = blockIdx.z;
    int zq = z / zdiv, zr = z % zdiv;
    A  += (long)zq * sA1 + (long)zr * sA2;
    Bm += (long)zq * sB1 + (long)zr * sB2;
    C  += (long)zq * sC1 + (long)zr * sC2;

    int t    = threadIdx.x;
    int lane = t & 31, w = t >> 5;
    int rowBase = blockIdx.y * 128;
    int colBase = blockIdx.x * 128;

    // ---- loader mapping: thread -> (row, 16-float half) of a 128x32 chunk
    int lrow = t >> 1, lhalf = t & 1;
    const float* gA = A + (long)(rowBase + lrow) * lda + lhalf * 16;
    const float* gB = Bm + (long)(colBase + lrow) * ldb + lhalf * 16;
    uint32_t sOff = (uint32_t)(lrow * SROW + lhalf * 16) * 4;  // bytes

    int NC = K >> 5;

    // prologue: stage 0 <- chunk 0
    {
        uint32_t dA = sbase + sOff;
        uint32_t dB = sbase + SZ * 4 + sOff;
        #pragma unroll
        for (int j = 0; j < 4; j++) {
            cp16(dA + j * 16, gA + j * 4);
            cp16(dB + j * 16, gB + j * 4);
        }
        CP_COMMIT();
    }

    // ---- compute mapping
    int mb = (w & 3) * 32;        // warp row within CTA tile
    int nb = (w >> 2) * 64;       // warp col within CTA tile
    int q  = lane >> 2, cl = lane & 3;

    float acc[2][8][4];
    #pragma unroll
    for (int i = 0; i < 2; i++)
        #pragma unroll
        for (int j = 0; j < 8; j++)
            #pragma unroll
            for (int u = 0; u < 4; u++) acc[i][j][u] = 0.0f;

    for (int c = 0; c < NC; c++) {
        int st = c & 1;
        if (c + 1 < NC) {
            int ns = (c + 1) & 1;
            uint32_t dA = sbase + (uint32_t)(ns * 2 * SZ) * 4 + sOff;
            uint32_t dB = dA + SZ * 4;
            const float* pA = gA + (c + 1) * 32;
            const float* pB = gB + (c + 1) * 32;
            #pragma unroll
            for (int j = 0; j < 4; j++) {
                cp16(dA + j * 16, pA + j * 4);
                cp16(dB + j * 16, pB + j * 4);
            }
            CP_COMMIT();
            CP_WAIT(1);
        } else {
            CP_WAIT(0);
        }
        __syncthreads();

        const float* sA = smem + st * 2 * SZ;
        const float* sB = sA + SZ;

        #pragma unroll
        for (int kk = 0; kk < 32; kk += 8) {
            uint32_t af[2][4];
            #pragma unroll
            for (int mt = 0; mt < 2; mt++) {
                const float* p = sA + (mb + mt * 16 + q) * SROW + kk + cl;
                af[mt][0] = f2tf(p[0]);
                af[mt][1] = f2tf(p[8 * SROW]);
                af[mt][2] = f2tf(p[4]);
                af[mt][3] = f2tf(p[8 * SROW + 4]);
            }
            uint32_t bf[8][2];
            #pragma unroll
            for (int nt = 0; nt < 8; nt++) {
                const float* p = sB + (nb + nt * 8 + q) * SROW + kk + cl;
                bf[nt][0] = f2tf(p[0]);
                bf[nt][1] = f2tf(p[4]);
            }
            #pragma unroll
            for (int mt = 0; mt < 2; mt++)
                #pragma unroll
                for (int nt = 0; nt < 8; nt++)
                    mma_tf32(acc[mt][nt], af[mt], bf[nt]);
        }
        __syncthreads();  // protect stage st from being overwritten next iter
    }

    // ---- epilogue
    #pragma unroll
    for (int mt = 0; mt < 2; mt++) {
        int r0 = rowBase + mb + mt * 16 + q;
        #pragma unroll
        for (int nt = 0; nt < 8; nt++) {
            int c0 = colBase + nb + nt * 8 + cl * 2;
            float b0 = 0.0f, b1 = 0.0f;
            if (bias) { b0 = bias[c0]; b1 = bias[c0 + 1]; }
            float v0 = (acc[mt][nt][0] + b0) * alpha;
            float v1 = (acc[mt][nt][1] + b1) * alpha;
            float v2 = (acc[mt][nt][2] + b0) * alpha;
            float v3 = (acc[mt][nt][3] + b1) * alpha;
            if (flags & 2) {
                v0 = fmaxf(v0, 0.0f); v1 = fmaxf(v1, 0.0f);
                v2 = fmaxf(v2, 0.0f); v3 = fmaxf(v3, 0.0f);
            }
            *(float2*)&C[(long)r0 * ldc + c0]       = make_float2(v0, v1);
            *(float2*)&C[(long)(r0 + 8) * ldc + c0] = make_float2(v2, v3);
        }
    }
}

// ---------------------------------------------------------------------------
// Tiled transpose: out[c,r] = in[r,c], with batch split strides.
// block (32,8), grid (C/32, R/32, Z)
// ---------------------------------------------------------------------------
__global__ void __launch_bounds__(256) transpose_k(
    const float* __restrict__ in, float* __restrict__ out,
    int ldin, int ldout,
    long sI1, long sI2, long sO1, long sO2, int zdiv)
{
    __shared__ float tile[32][33];
    int z = blockIdx.z;
    int zq = z / zdiv, zr = z % zdiv;
    in  += (long)zq * sI1 + (long)zr * sI2;
    out += (long)zq * sO1 + (long)zr * sO2;
    int r0 = blockIdx.y * 32, c0 = blockIdx.x * 32;
    int tx = threadIdx.x, ty = threadIdx.y;
    #pragma unroll
    for (int i = 0; i < 32; i += 8)
        tile[ty + i][tx] = in[(long)(r0 + ty + i) * ldin + c0 + tx];
    __syncthreads();
    #pragma unroll
    for (int i = 0; i < 32; i += 8)
        out[(long)(c0 + ty + i) * ldout + r0 + tx] = tile[tx][ty + i];
}

// ---------------------------------------------------------------------------
// Row softmax over rows of length Tc=1024. One block (256 thr) per row.
// ---------------------------------------------------------------------------
__global__ void __launch_bounds__(256) softmax_k(float* __restrict__ S)
{
    float* row = S + (long)blockIdx.x * Tc;
    int t = threadIdx.x;
    float4 v = *(float4*)&row[t * 4];

    __shared__ float red[8];

    float m = fmaxf(fmaxf(v.x, v.y), fmaxf(v.z, v.w));
    #pragma unroll
    for (int o = 16; o > 0; o >>= 1) m = fmaxf(m, __shfl_xor_sync(0xffffffffu, m, o));
    if ((t & 31) == 0) red[t >> 5] = m;
    __syncthreads();
    m = red[0];
    #pragma unroll
    for (int w = 1; w < 8; w++) m = fmaxf(m, red[w]);

    v.x = __expf(v.x - m); v.y = __expf(v.y - m);
    v.z = __expf(v.z - m); v.w = __expf(v.w - m);
    float s = v.x + v.y + v.z + v.w;
    #pragma unroll
    for (int o = 16; o > 0; o >>= 1) s += __shfl_xor_sync(0xffffffffu, s, o);
    __syncthreads();
    if ((t & 31) == 0) red[t >> 5] = s;
    __syncthreads();
    s = 0.0f;
    #pragma unroll
    for (int w = 0; w < 8; w++) s += red[w];

    float inv = 1.0f / s;
    v.x *= inv; v.y *= inv; v.z *= inv; v.w *= inv;
    *(float4*)&row[t * 4] = v;
}

// ---------------------------------------------------------------------------
// Fused residual + LayerNorm
// ---------------------------------------------------------------------------
__global__ void __launch_bounds__(256) ln_k(
    const float* __restrict__ a, const float* __restrict__ res,
    const float* __restrict__ sg, const float* __restrict__ bg,
    float* __restrict__ out)
{
    long r = blockIdx.x;
    int  t = threadIdx.x;
    float v = a[r * Dc + t] + res[r * Dc + t];

    __shared__ float red[8];

    float s = v;
    #pragma unroll
    for (int o = 16; o > 0; o >>= 1) s += __shfl_xor_sync(0xffffffffu, s, o);
    if ((t & 31) == 0) red[t >> 5] = s;
    __syncthreads();
    s = 0.0f;
    #pragma unroll
    for (int w = 0; w < 8; w++) s += red[w];
    float mean = s * (1.0f / Dc);

    float d = v - mean;
    float q = d * d;
    #pragma unroll
    for (int o = 16; o > 0; o >>= 1) q += __shfl_xor_sync(0xffffffffu, q, o);
    __syncthreads();
    if ((t & 31) == 0) red[t >> 5] = q;
    __syncthreads();
    q = 0.0f;
    #pragma unroll
    for (int w = 0; w < 8; w++) q += red[w];
    float var = q * (1.0f / Dc);

    out[r * Dc + t] = d * rsqrtf(var + LN_EPS) * sg[t] + bg[t];
}

// ---------------------------------------------------------------------------
// Launch
// ---------------------------------------------------------------------------
extern "C" void kernel_launch(void* const* d_in, const int* in_sizes, int n_in,
                              void* d_out, int out_size)
{
    const float* queries = (const float*)d_in[0];
    const float* Wq   = (const float*)d_in[1];
    const float* bq   = (const float*)d_in[2];
    const float* Wk   = (const float*)d_in[3];
    const float* bk   = (const float*)d_in[4];
    const float* Wv   = (const float*)d_in[5];
    const float* bv   = (const float*)d_in[6];
    const float* Wo   = (const float*)d_in[7];
    const float* bo   = (const float*)d_in[8];
    const float* ln1s = (const float*)d_in[9];
    const float* ln1b = (const float*)d_in[10];
    const float* W1   = (const float*)d_in[11];
    const float* b1   = (const float*)d_in[12];
    const float* W2   = (const float*)d_in[13];
    const float* b2   = (const float*)d_in[14];
    const float* ln2s = (const float*)d_in[15];
    const float* ln2b = (const float*)d_in[16];

    static bool attr_set = false;
    cudaFuncSetAttribute(gemm_mma, cudaFuncAttributeMaxDynamicSharedMemorySize, GT_SMEM);
    (void)attr_set;

    float *x, *q, *k, *v, *vt, *ao, *h, *proj, *sc;
    float *wqT, *wkT, *wvT, *woT, *w1T, *w2T;
    cudaGetSymbolAddress((void**)&x,    g_x);
    cudaGetSymbolAddress((void**)&q,    g_q);
    cudaGetSymbolAddress((void**)&k,    g_k);
    cudaGetSymbolAddress((void**)&v,    g_v);
    cudaGetSymbolAddress((void**)&vt,   g_vt);
    cudaGetSymbolAddress((void**)&ao,   g_ao);
    cudaGetSymbolAddress((void**)&h,    g_h);
    cudaGetSymbolAddress((void**)&proj, g_proj);
    cudaGetSymbolAddress((void**)&sc,   g_s);
    cudaGetSymbolAddress((void**)&wqT,  g_wqT);
    cudaGetSymbolAddress((void**)&wkT,  g_wkT);
    cudaGetSymbolAddress((void**)&wvT,  g_wvT);
    cudaGetSymbolAddress((void**)&woT,  g_woT);
    cudaGetSymbolAddress((void**)&w1T,  g_w1T);
    cudaGetSymbolAddress((void**)&w2T,  g_w2T);

    const float* xin = queries;
    const float qscale = 1.0f / 16.0f;
    dim3 tb(32, 8, 1);

    for (int l = 0; l < Lc; l++) {
        const float* wq  = Wq + (long)l * Dc * HD;
        const float* wk  = Wk + (long)l * Dc * HD;
        const float* wv  = Wv + (long)l * Dc * HD;
        const float* wo  = Wo + (long)l * HD * Dc;
        const float* w1  = W1 + (long)l * Dc * Mc;
        const float* w2  = W2 + (long)l * Mc * Dc;
        const float* bql = bq + (long)l * HD;
        const float* bkl = bk + (long)l * HD;
        const float* bvl = bv + (long)l * HD;
        const float* bol = bo + (long)l * Dc;
        const float* b1l = b1 + (long)l * Mc;
        const float* b2l = b2 + (long)l * Dc;
        const float* s1l = ln1s + (long)l * Dc;
        const float* o1l = ln1b + (long)l * Dc;
        const float* s2l = ln2s + (long)l * Dc;
        const float* o2l = ln2b + (long)l * Dc;

        // Weight transposes to [N,K] K-major
        transpose_k<<<dim3(HD/32, Dc/32, 1), tb>>>(wq, wqT, HD, Dc, 0,0,0,0, 1);
        transpose_k<<<dim3(HD/32, Dc/32, 1), tb>>>(wk, wkT, HD, Dc, 0,0,0,0, 1);
        transpose_k<<<dim3(HD/32, Dc/32, 1), tb>>>(wv, wvT, HD, Dc, 0,0,0,0, 1);
        transpose_k<<<dim3(Dc/32, HD/32, 1), tb>>>(wo, woT, Dc, HD, 0,0,0,0, 1);
        transpose_k<<<dim3(Mc/32, Dc/32, 1), tb>>>(w1, w1T, Mc, Dc, 0,0,0,0, 1);
        transpose_k<<<dim3(Dc/32, Mc/32, 1), tb>>>(w2, w2T, Dc, Mc, 0,0,0,0, 1);

        // QKV projections: [4096,256] x [256,1024]
        gemm_mma<<<dim3(HD/128, NROWS/128, 1), 256, GT_SMEM>>>(xin, wqT, q, bql,
            Dc, Dc, Dc, HD, 0,0,0,0,0,0, 1, qscale, 0);
        gemm_mma<<<dim3(HD/128, NROWS/128, 1), 256, GT_SMEM>>>(xin, wkT, k, bkl,
            Dc, Dc, Dc, HD, 0,0,0,0,0,0, 1, 1.0f, 0);
        gemm_mma<<<dim3(HD/128, NROWS/128, 1), 256, GT_SMEM>>>(xin, wvT, v, bvl,
            Dc, Dc, Dc, HD, 0,0,0,0,0,0, 1, 1.0f, 0);

        // scores[b,h] = q @ k^T  (K naturally [N,K] K-major)
        gemm_mma<<<dim3(Tc/128, Tc/128, Bc*Hc), 256, GT_SMEM>>>(q, k, sc, nullptr,
            Dc, HD, HD, Tc,
            (long)Tc*HD, (long)Dc,
            (long)Tc*HD, (long)Dc,
            (long)Hc*Tc*Tc, (long)Tc*Tc,
            Hc, 1.0f, 0);

        softmax_k<<<Bc*Hc*Tc, 256>>>(sc);

        // V transpose per (b,h): [1024,256] -> [256,1024]
        transpose_k<<<dim3(Dc/32, Tc/32, Bc*Hc), tb>>>(v, vt, HD, Tc,
            (long)Tc*HD, (long)Dc,
            (long)Hc*Dc*Tc, (long)Dc*Tc, Hc);

        // out[b,:,h,:] = scores[b,h] @ V[b,h]
        gemm_mma<<<dim3(Dc/128, Tc/128, Bc*Hc), 256, GT_SMEM>>>(sc, vt, ao, nullptr,
            Tc, Tc, Tc, HD,
            (long)Hc*Tc*Tc, (long)Tc*Tc,
            (long)Hc*Dc*Tc, (long)Dc*Tc,
            (long)Tc*HD, (long)Dc,
            Hc, 1.0f, 0);

        // output projection: [4096,1024] x [1024,256]
        gemm_mma<<<dim3(Dc/128, NROWS/128, 1), 256, GT_SMEM>>>(ao, woT, proj, bol,
            HD, HD, HD, Dc, 0,0,0,0,0,0, 1, 1.0f, 0);

        ln_k<<<NROWS, 256>>>(proj, xin, s1l, o1l, x);

        // MLP
        gemm_mma<<<dim3(Mc/128, NROWS/128, 1), 256, GT_SMEM>>>(x, w1T, h, b1l,
            Dc, Dc, Dc, Mc, 0,0,0,0,0,0, 1, 1.0f, 2 /*ReLU*/);
        gemm_mma<<<dim3(Dc/128, NROWS/128, 1), 256, GT_SMEM>>>(h, w2T, proj, b2l,
            Mc, Mc, Mc, Dc, 0,0,0,0,0,0, 1, 1.0f, 0);

        float* lnout = (l == Lc - 1) ? (float*)d_out : x;
        ln_k<<<NROWS, 256>>>(proj, x, s2l, o2l, lnout);

        xin = x;
    }
}

// round 4
// speedup vs baseline: 4.8631x; 2.1893x over previous
#include <cuda_runtime.h>
#include <cuda_fp16.h>
#include <cstdint>
#include <math.h>

// Problem constants
#define Lc 2
#define Bc 4
#define Tc 1024
#define Dc 256
#define Hc 4
#define Mc 1024
#define NROWS (Bc*Tc)      // 4096
#define HD (Hc*Dc)         // 1024
#define LN_EPS 1e-5f

// ---------------------------------------------------------------------------
// Scratch (device globals; allocation-free contract)
// ---------------------------------------------------------------------------
__device__ float  g_x[NROWS*Dc];
__device__ float  g_proj[NROWS*Dc];
__device__ float  g_s[(long)Bc*Hc*Tc*Tc];      // fp32 attention scores (64MB)
__device__ __half g_xh[NROWS*Dc];
__device__ __half g_qh[NROWS*HD];
__device__ __half g_kh[NROWS*HD];
__device__ __half g_vh[NROWS*HD];
__device__ __half g_aoh[NROWS*HD];
__device__ __half g_hh[NROWS*Mc];
__device__ __half g_ph[(long)Bc*Hc*Tc*Tc];     // half probs (32MB)
__device__ __half g_wqh[Dc*HD];
__device__ __half g_wkh[Dc*HD];
__device__ __half g_wvh[Dc*HD];
__device__ __half g_woh[HD*Dc];
__device__ __half g_w1h[Dc*Mc];
__device__ __half g_w2h[Mc*Dc];

// ---------------------------------------------------------------------------
// Helpers
// ---------------------------------------------------------------------------
__device__ __forceinline__ uint32_t smem_u32(const void* p) {
    uint32_t a;
    asm("{ .reg .u64 t; cvta.to.shared.u64 t, %1; cvt.u32.u64 %0, t; }"
        : "=r"(a) : "l"(p));
    return a;
}
__device__ __forceinline__ void cp16(uint32_t dst, const void* src) {
    asm volatile("cp.async.cg.shared.global [%0], [%1], 16;"
                 :: "r"(dst), "l"(src) : "memory");
}
#define CP_COMMIT() asm volatile("cp.async.commit_group;" ::: "memory")
#define CP_WAIT(n)  asm volatile("cp.async.wait_group %0;" :: "n"(n) : "memory")

#define LDSM4(r, addr) \
    asm volatile("ldmatrix.sync.aligned.m8n8.x4.shared.b16 {%0,%1,%2,%3}, [%4];" \
        : "=r"((r)[0]), "=r"((r)[1]), "=r"((r)[2]), "=r"((r)[3]) : "r"(addr))
#define LDSM4T(r, addr) \
    asm volatile("ldmatrix.sync.aligned.m8n8.x4.trans.shared.b16 {%0,%1,%2,%3}, [%4];" \
        : "=r"((r)[0]), "=r"((r)[1]), "=r"((r)[2]), "=r"((r)[3]) : "r"(addr))

__device__ __forceinline__ void mma_f16(float* c, const uint32_t* a,
                                        uint32_t b0, uint32_t b1) {
    asm volatile(
        "mma.sync.aligned.m16n8k16.row.col.f32.f16.f16.f32 "
        "{%0,%1,%2,%3}, {%4,%5,%6,%7}, {%8,%9}, {%0,%1,%2,%3};"
        : "+f"(c[0]), "+f"(c[1]), "+f"(c[2]), "+f"(c[3])
        : "r"(a[0]), "r"(a[1]), "r"(a[2]), "r"(a[3]), "r"(b0), "r"(b1));
}

// ---------------------------------------------------------------------------
// fp16 mma GEMM: C[m,n] = op(alpha*(sum_k A[m,k]*B[n/k...] + bias[n]))
//   MT = CTA rows (64 or 128), CTA cols fixed 128. BK=32. 8 warps.
//   TB=false: B is [N,K] K-major (row stride ldb)         -> ldmatrix
//   TB=true : B is [K,N] N-major (row stride ldb)         -> ldmatrix.trans
// flags bit1 = ReLU. Cf (fp32) / Ch (half) outputs, either may be null.
// Batch via blockIdx.z with split strides (z = zq*zdiv + zr).
// SMEM padded strides: A/Bnk rows 80B (40 half), Bkn rows 272B (136 half).
// ---------------------------------------------------------------------------
#define BSZ 10240
template<int MT, bool TB>
__global__ void __launch_bounds__(256, 2) gemm_h(
    const __half* __restrict__ A, const __half* __restrict__ B,
    float* __restrict__ Cf, __half* __restrict__ Ch, const float* __restrict__ bias,
    int K, int lda, int ldb, int ldc,
    long sA1, long sA2, long sB1, long sB2, long sC1, long sC2,
    int zdiv, float alpha, int flags)
{
    constexpr int ASZ = MT * 80;        // bytes per A stage
    constexpr int STG = ASZ + BSZ;      // bytes per stage
    constexpr int NA  = (MT == 128) ? 2 : 1;
    constexpr int NPAIR = (MT == 128) ? 4 : 2;
    constexpr int NT  = NPAIR * 2;

    extern __shared__ char smem[];
    uint32_t sbase = smem_u32(smem);

    int z  = blockIdx.z;
    int zq = z / zdiv, zr = z % zdiv;
    A  += (long)zq * sA1 + (long)zr * sA2;
    B  += (long)zq * sB1 + (long)zr * sB2;
    if (Cf) Cf += (long)zq * sC1 + (long)zr * sC2;
    if (Ch) Ch += (long)zq * sC1 + (long)zr * sC2;

    int t    = threadIdx.x;
    int lane = t & 31, w = t >> 5;
    int rowBase = blockIdx.y * MT;
    int colBase = blockIdx.x * 128;

    // ---- loader mappings
    const __half* pA[2]; uint32_t sa[2];
    const __half* pB[2]; uint32_t sb[2];
    #pragma unroll
    for (int i = 0; i < NA; i++) {
        int idx = t + i * 256;
        int ar = idx >> 2, ac = idx & 3;
        pA[i] = A + (long)(rowBase + ar) * lda + ac * 8;
        sa[i] = (uint32_t)(ar * 80 + ac * 16);
    }
    #pragma unroll
    for (int i = 0; i < 2; i++) {
        int idx = t + i * 256;
        if (TB) {
            int kr = idx >> 4, nc = idx & 15;
            pB[i] = B + (long)kr * ldb + colBase + nc * 8;
            sb[i] = (uint32_t)(kr * 272 + nc * 16);
        } else {
            int br = idx >> 2, bc = idx & 3;
            pB[i] = B + (long)(colBase + br) * ldb + bc * 8;
            sb[i] = (uint32_t)(br * 80 + bc * 16);
        }
    }
    const long bAdv = TB ? 32L * ldb : 32L;

    int NC = K >> 5;

    // prologue: stage 0 <- chunk 0
    {
        uint32_t base = sbase;
        #pragma unroll
        for (int i = 0; i < NA; i++) cp16(base + sa[i], pA[i]);
        #pragma unroll
        for (int i = 0; i < 2; i++)  cp16(base + ASZ + sb[i], pB[i]);
        CP_COMMIT();
    }

    // ---- compute mapping
    int mb, nb;
    if (MT == 128) { mb = (w & 3) * 32; nb = (w >> 2) * 64; }
    else           { mb = (w & 1) * 32; nb = (w >> 1) * 32; }
    int g  = lane >> 3, lr = lane & 7;
    int qr = lane >> 2, cl = lane & 3;

    float acc[2][NT][4];
    #pragma unroll
    for (int i = 0; i < 2; i++)
        #pragma unroll
        for (int j = 0; j < NT; j++)
            #pragma unroll
            for (int u = 0; u < 4; u++) acc[i][j][u] = 0.0f;

    for (int c = 0; c < NC; c++) {
        int st = c & 1;
        if (c + 1 < NC) {
            uint32_t base = sbase + ((c + 1) & 1) * STG;
            #pragma unroll
            for (int i = 0; i < NA; i++) cp16(base + sa[i], pA[i] + (c + 1) * 32);
            #pragma unroll
            for (int i = 0; i < 2; i++)  cp16(base + ASZ + sb[i], pB[i] + (c + 1) * bAdv);
            CP_COMMIT();
            CP_WAIT(1);
        } else {
            CP_WAIT(0);
        }
        __syncthreads();

        uint32_t As = sbase + st * STG;
        uint32_t Bs = As + ASZ;

        #pragma unroll
        for (int kk = 0; kk < 32; kk += 16) {
            uint32_t af[2][4];
            #pragma unroll
            for (int mt = 0; mt < 2; mt++) {
                uint32_t addr = As + (uint32_t)((mb + mt * 16 + (g & 1) * 8 + lr) * 80
                                                + ((g >> 1) * 8 + kk) * 2);
                LDSM4(af[mt], addr);
            }
            #pragma unroll
            for (int np = 0; np < NPAIR; np++) {
                uint32_t bf[4];
                if (TB) {
                    uint32_t addr = Bs + (uint32_t)((kk + (g & 1) * 8 + lr) * 272
                                                    + (nb + np * 16 + (g >> 1) * 8) * 2);
                    LDSM4T(bf, addr);
                } else {
                    uint32_t addr = Bs + (uint32_t)((nb + np * 16 + (g >> 1) * 8 + lr) * 80
                                                    + ((g & 1) * 8 + kk) * 2);
                    LDSM4(bf, addr);
                }
                mma_f16(acc[0][np * 2 + 0], af[0], bf[0], bf[1]);
                mma_f16(acc[0][np * 2 + 1], af[0], bf[2], bf[3]);
                mma_f16(acc[1][np * 2 + 0], af[1], bf[0], bf[1]);
                mma_f16(acc[1][np * 2 + 1], af[1], bf[2], bf[3]);
            }
        }
        __syncthreads();
    }

    // ---- epilogue
    #pragma unroll
    for (int mt = 0; mt < 2; mt++) {
        int r0 = rowBase + mb + mt * 16 + qr;
        #pragma unroll
        for (int nt = 0; nt < NT; nt++) {
            int c0 = colBase + nb + nt * 8 + cl * 2;
            float b0 = 0.0f, b1 = 0.0f;
            if (bias) { b0 = bias[c0]; b1 = bias[c0 + 1]; }
            float v0 = (acc[mt][nt][0] + b0) * alpha;
            float v1 = (acc[mt][nt][1] + b1) * alpha;
            float v2 = (acc[mt][nt][2] + b0) * alpha;
            float v3 = (acc[mt][nt][3] + b1) * alpha;
            if (flags & 2) {
                v0 = fmaxf(v0, 0.0f); v1 = fmaxf(v1, 0.0f);
                v2 = fmaxf(v2, 0.0f); v3 = fmaxf(v3, 0.0f);
            }
            if (Cf) {
                *(float2*)&Cf[(long)r0 * ldc + c0]       = make_float2(v0, v1);
                *(float2*)&Cf[(long)(r0 + 8) * ldc + c0] = make_float2(v2, v3);
            }
            if (Ch) {
                *(__half2*)&Ch[(long)r0 * ldc + c0]       = __floats2half2_rn(v0, v1);
                *(__half2*)&Ch[(long)(r0 + 8) * ldc + c0] = __floats2half2_rn(v2, v3);
            }
        }
    }
}

// ---------------------------------------------------------------------------
// fp32 -> fp16 convert (vectorized x4). n multiple of 1024.
// ---------------------------------------------------------------------------
__global__ void __launch_bounds__(256) cvt_k(const float* __restrict__ in,
                                            __half* __restrict__ out)
{
    int i = (blockIdx.x * 256 + threadIdx.x) * 4;
    float4 v = *(const float4*)&in[i];
    *(__half2*)&out[i]     = __floats2half2_rn(v.x, v.y);
    *(__half2*)&out[i + 2] = __floats2half2_rn(v.z, v.w);
}

// ---------------------------------------------------------------------------
// Row softmax, fp32 scores -> half probs. One block (256 thr) per row (Tc).
// ---------------------------------------------------------------------------
__global__ void __launch_bounds__(256) softmax_k(const float* __restrict__ S,
                                                 __half* __restrict__ P)
{
    const float* row = S + (long)blockIdx.x * Tc;
    __half* prow = P + (long)blockIdx.x * Tc;
    int t = threadIdx.x;
    float4 v = *(const float4*)&row[t * 4];

    __shared__ float red[8];

    float m = fmaxf(fmaxf(v.x, v.y), fmaxf(v.z, v.w));
    #pragma unroll
    for (int o = 16; o > 0; o >>= 1) m = fmaxf(m, __shfl_xor_sync(0xffffffffu, m, o));
    if ((t & 31) == 0) red[t >> 5] = m;
    __syncthreads();
    m = red[0];
    #pragma unroll
    for (int w = 1; w < 8; w++) m = fmaxf(m, red[w]);

    v.x = __expf(v.x - m); v.y = __expf(v.y - m);
    v.z = __expf(v.z - m); v.w = __expf(v.w - m);
    float s = v.x + v.y + v.z + v.w;
    #pragma unroll
    for (int o = 16; o > 0; o >>= 1) s += __shfl_xor_sync(0xffffffffu, s, o);
    __syncthreads();
    if ((t & 31) == 0) red[t >> 5] = s;
    __syncthreads();
    s = 0.0f;
    #pragma unroll
    for (int w = 0; w < 8; w++) s += red[w];

    float inv = 1.0f / s;
    *(__half2*)&prow[t * 4]     = __floats2half2_rn(v.x * inv, v.y * inv);
    *(__half2*)&prow[t * 4 + 2] = __floats2half2_rn(v.z * inv, v.w * inv);
}

// ---------------------------------------------------------------------------
// Fused residual + LayerNorm, dual fp32 + fp16 output
// ---------------------------------------------------------------------------
__global__ void __launch_bounds__(256) ln_k(
    const float* __restrict__ a, const float* __restrict__ res,
    const float* __restrict__ sg, const float* __restrict__ bg,
    float* __restrict__ outF, __half* __restrict__ outH)
{
    long r = blockIdx.x;
    int  t = threadIdx.x;
    float v = a[r * Dc + t] + res[r * Dc + t];

    __shared__ float red[8];

    float s = v;
    #pragma unroll
    for (int o = 16; o > 0; o >>= 1) s += __shfl_xor_sync(0xffffffffu, s, o);
    if ((t & 31) == 0) red[t >> 5] = s;
    __syncthreads();
    s = 0.0f;
    #pragma unroll
    for (int w = 0; w < 8; w++) s += red[w];
    float mean = s * (1.0f / Dc);

    float d = v - mean;
    float q = d * d;
    #pragma unroll
    for (int o = 16; o > 0; o >>= 1) q += __shfl_xor_sync(0xffffffffu, q, o);
    __syncthreads();
    if ((t & 31) == 0) red[t >> 5] = q;
    __syncthreads();
    q = 0.0f;
    #pragma unroll
    for (int w = 0; w < 8; w++) q += red[w];
    float var = q * (1.0f / Dc);

    float o = d * rsqrtf(var + LN_EPS) * sg[t] + bg[t];
    outF[r * Dc + t] = o;
    outH[r * Dc + t] = __float2half_rn(o);
}

// ---------------------------------------------------------------------------
// Launch
// ---------------------------------------------------------------------------
extern "C" void kernel_launch(void* const* d_in, const int* in_sizes, int n_in,
                              void* d_out, int out_size)
{
    const float* queries = (const float*)d_in[0];
    const float* Wq   = (const float*)d_in[1];
    const float* bq   = (const float*)d_in[2];
    const float* Wk   = (const float*)d_in[3];
    const float* bk   = (const float*)d_in[4];
    const float* Wv   = (const float*)d_in[5];
    const float* bv   = (const float*)d_in[6];
    const float* Wo   = (const float*)d_in[7];
    const float* bo   = (const float*)d_in[8];
    const float* ln1s = (const float*)d_in[9];
    const float* ln1b = (const float*)d_in[10];
    const float* W1   = (const float*)d_in[11];
    const float* b1   = (const float*)d_in[12];
    const float* W2   = (const float*)d_in[13];
    const float* b2   = (const float*)d_in[14];
    const float* ln2s = (const float*)d_in[15];
    const float* ln2b = (const float*)d_in[16];

    float *x, *proj, *sc;
    __half *xh, *qh, *kh, *vh, *aoh, *hh, *ph;
    __half *wqh, *wkh, *wvh, *woh, *w1h, *w2h;
    cudaGetSymbolAddress((void**)&x,    g_x);
    cudaGetSymbolAddress((void**)&proj, g_proj);
    cudaGetSymbolAddress((void**)&sc,   g_s);
    cudaGetSymbolAddress((void**)&xh,   g_xh);
    cudaGetSymbolAddress((void**)&qh,   g_qh);
    cudaGetSymbolAddress((void**)&kh,   g_kh);
    cudaGetSymbolAddress((void**)&vh,   g_vh);
    cudaGetSymbolAddress((void**)&aoh,  g_aoh);
    cudaGetSymbolAddress((void**)&hh,   g_hh);
    cudaGetSymbolAddress((void**)&ph,   g_ph);
    cudaGetSymbolAddress((void**)&wqh,  g_wqh);
    cudaGetSymbolAddress((void**)&wkh,  g_wkh);
    cudaGetSymbolAddress((void**)&wvh,  g_wvh);
    cudaGetSymbolAddress((void**)&woh,  g_woh);
    cudaGetSymbolAddress((void**)&w1h,  g_w1h);
    cudaGetSymbolAddress((void**)&w2h,  g_w2h);

    const int SM128 = 2 * (128 * 80 + BSZ);  // 40960
    const int SM64  = 2 * (64 * 80 + BSZ);   // 30720

    const float* xin = queries;
    const float qscale = 1.0f / 16.0f;

    // queries -> half (once)
    cvt_k<<<NROWS*Dc/1024, 256>>>(queries, xh);

    for (int l = 0; l < Lc; l++) {
        const float* wq  = Wq + (long)l * Dc * HD;
        const float* wk  = Wk + (long)l * Dc * HD;
        const float* wv  = Wv + (long)l * Dc * HD;
        const float* wo  = Wo + (long)l * HD * Dc;
        const float* w1  = W1 + (long)l * Dc * Mc;
        const float* w2  = W2 + (long)l * Mc * Dc;
        const float* bql = bq + (long)l * HD;
        const float* bkl = bk + (long)l * HD;
        const float* bvl = bv + (long)l * HD;
        const float* bol = bo + (long)l * Dc;
        const float* b1l = b1 + (long)l * Mc;
        const float* b2l = b2 + (long)l * Dc;
        const float* s1l = ln1s + (long)l * Dc;
        const float* o1l = ln1b + (long)l * Dc;
        const float* s2l = ln2s + (long)l * Dc;
        const float* o2l = ln2b + (long)l * Dc;

        // Weight converts to half ([K,N] layout kept as-is)
        cvt_k<<<Dc*HD/1024, 256>>>(wq, wqh);
        cvt_k<<<Dc*HD/1024, 256>>>(wk, wkh);
        cvt_k<<<Dc*HD/1024, 256>>>(wv, wvh);
        cvt_k<<<HD*Dc/1024, 256>>>(wo, woh);
        cvt_k<<<Dc*Mc/1024, 256>>>(w1, w1h);
        cvt_k<<<Mc*Dc/1024, 256>>>(w2, w2h);

        // QKV projections: [4096,256] x [256,1024], B=[K,N]
        gemm_h<128,true><<<dim3(HD/128, NROWS/128, 1), 256, SM128>>>(
            xh, wqh, nullptr, qh, bql, Dc, Dc, HD, HD,
            0,0,0,0,0,0, 1, qscale, 0);
        gemm_h<128,true><<<dim3(HD/128, NROWS/128, 1), 256, SM128>>>(
            xh, wkh, nullptr, kh, bkl, Dc, Dc, HD, HD,
            0,0,0,0,0,0, 1, 1.0f, 0);
        gemm_h<128,true><<<dim3(HD/128, NROWS/128, 1), 256, SM128>>>(
            xh, wvh, nullptr, vh, bvl, Dc, Dc, HD, HD,
            0,0,0,0,0,0, 1, 1.0f, 0);

        // scores[b,h] = q @ k^T  (B=K matrix is [N,K] K-major) -> fp32
        gemm_h<128,false><<<dim3(Tc/128, Tc/128, Bc*Hc), 256, SM128>>>(
            qh, kh, sc, nullptr, nullptr, Dc, HD, HD, Tc,
            (long)Tc*HD, (long)Dc,
            (long)Tc*HD, (long)Dc,
            (long)Hc*Tc*Tc, (long)Tc*Tc,
            Hc, 1.0f, 0);

        softmax_k<<<Bc*Hc*Tc, 256>>>(sc, ph);

        // out[b,:,h,:] = probs[b,h] @ V[b,h]   (V is [K=s, N=d] with row stride HD)
        gemm_h<128,true><<<dim3(Dc/128, Tc/128, Bc*Hc), 256, SM128>>>(
            ph, vh, nullptr, aoh, nullptr, Tc, Tc, HD, HD,
            (long)Hc*Tc*Tc, (long)Tc*Tc,
            (long)Tc*HD, (long)Dc,
            (long)Tc*HD, (long)Dc,
            Hc, 1.0f, 0);

        // output projection: [4096,1024] x [1024,256] (64-row tiles: 128 CTAs)
        gemm_h<64,true><<<dim3(Dc/128, NROWS/64, 1), 256, SM64>>>(
            aoh, woh, proj, nullptr, bol, HD, HD, Dc, Dc,
            0,0,0,0,0,0, 1, 1.0f, 0);

        ln_k<<<NROWS, 256>>>(proj, xin, s1l, o1l, x, xh);

        // MLP
        gemm_h<128,true><<<dim3(Mc/128, NROWS/128, 1), 256, SM128>>>(
            xh, w1h, nullptr, hh, b1l, Dc, Dc, Mc, Mc,
            0,0,0,0,0,0, 1, 1.0f, 2 /*ReLU*/);
        gemm_h<64,true><<<dim3(Dc/128, NROWS/64, 1), 256, SM64>>>(
            hh, w2h, proj, nullptr, b2l, Mc, Mc, Dc, Dc,
            0,0,0,0,0,0, 1, 1.0f, 0);

        float* lnout = (l == Lc - 1) ? (float*)d_out : x;
        ln_k<<<NROWS, 256>>>(proj, x, s2l, o2l, lnout, xh);

        xin = x;
    }
}